// round 7
// baseline (speedup 1.0000x reference)
#include <cuda_runtime.h>

static constexpr int DIM   = 8;
static constexpr int PATCH = 16;
static constexpr int NPAIR = PATCH - 1;
static constexpr int W     = 2 * DIM;

__device__ __forceinline__ unsigned long long pack2(float lo, float hi) {
    unsigned long long r;
    asm("mov.b64 %0, {%1, %2};" : "=l"(r) : "f"(lo), "f"(hi));
    return r;
}
__device__ __forceinline__ unsigned long long fma2(unsigned long long a,
                                                   unsigned long long b,
                                                   unsigned long long c) {
    unsigned long long d;
    asm("fma.rn.f32x2 %0, %1, %2, %3;" : "=l"(d) : "l"(a), "l"(b), "l"(c));
    return d;
}

// Thread t (128/block): p = t>>3 (0..15), q = t&7. Thread owns signature
// cells (p,q) and (p,q+8); both share s1 = S1[p]. p<8 is warp-uniform.
template <bool AL>
__device__ __forceinline__ void mainloop(
    const float (*__restrict__ sd)[DIM],
    int pl, int q,
    float& s1, float& s2A, float& s2C,
    unsigned long long* __restrict__ vA,
    unsigned long long* __restrict__ vC)
{
    #pragma unroll
    for (int k = 0; k < NPAIR; k++) {
        const ulonglong2* sdv = reinterpret_cast<const ulonglong2*>(sd[k]);
        const ulonglong2 dA = sdv[0];
        const ulonglong2 dB = sdv[1];
        const float dp = sd[k][pl];
        const float dq = sd[k][q];

        float coefAL, coefAG, coefCL, coefCG;
        if (AL) {
            // p<8: p active in LEAD. Cell A (b=q) active in LEAD, C (b=q+8) in LAG.
            float tt = dp * dq;
            float pa = s1 * dq;
            coefAL = fmaf(0.5f, pa, s2A);
            coefAL = fmaf(1.0f / 6.0f, tt, coefAL);
            coefCL = s2C;
            s2A    = s2A + pa;
            s2A    = fmaf(0.5f, tt, s2A);
            s1    += dp;
            float pc = s1 * dq;           // lag: uses updated s1
            coefAG = s2A;
            coefCG = fmaf(0.5f, pc, s2C);
            s2C   += pc;
        } else {
            // p>=8: p active in LAG.
            float pa = s1 * dq;           // lead: pre-update s1
            coefAL = fmaf(0.5f, pa, s2A);
            coefCL = s2C;
            s2A   += pa;
            coefAG = s2A;
            float tt = dp * dq;
            float pc = s1 * dq;
            coefCG = fmaf(0.5f, pc, s2C);
            coefCG = fmaf(1.0f / 6.0f, tt, coefCG);
            s2C   += pc;
            s2C    = fmaf(0.5f, tt, s2C);
            s1    += dp;
        }

        const unsigned long long cAL = pack2(coefAL, coefAL);
        const unsigned long long cAG = pack2(coefAG, coefAG);
        const unsigned long long cCL = pack2(coefCL, coefCL);
        const unsigned long long cCG = pack2(coefCG, coefCG);

        vA[0] = fma2(cAL, dA.x, vA[0]);  vA[1] = fma2(cAL, dA.y, vA[1]);
        vA[2] = fma2(cAL, dB.x, vA[2]);  vA[3] = fma2(cAL, dB.y, vA[3]);
        vA[4] = fma2(cAG, dA.x, vA[4]);  vA[5] = fma2(cAG, dA.y, vA[5]);
        vA[6] = fma2(cAG, dB.x, vA[6]);  vA[7] = fma2(cAG, dB.y, vA[7]);

        vC[0] = fma2(cCL, dA.x, vC[0]);  vC[1] = fma2(cCL, dA.y, vC[1]);
        vC[2] = fma2(cCL, dB.x, vC[2]);  vC[3] = fma2(cCL, dB.y, vC[3]);
        vC[4] = fma2(cCG, dA.x, vC[4]);  vC[5] = fma2(cCG, dA.y, vC[5]);
        vC[6] = fma2(cCG, dB.x, vC[6]);  vC[7] = fma2(cCG, dB.y, vC[7]);
    }
}

// Conflict-free chunk swizzle for both STS (fixed-p 8-lane phases) and the
// linear LDS sweep.
__device__ __forceinline__ int swz(int c) {
    return c ^ ((c >> 3) & 7);
}

__global__ __launch_bounds__(128, 16)
void leadlag_sig_kernel(const float* __restrict__ x,
                        float* __restrict__ out,
                        int seq_len)
{
    const int i = blockIdx.x;
    const int t = threadIdx.x;       // 0..127
    const int p = t >> 3;            // first index 0..15 (warp-uniform half)
    const int q = t & 7;             // second index low part

    __shared__ __align__(16) float sd[NPAIR][DIM];
    __shared__ __align__(16) ulonglong2 sbuf[512];     // 8 KB transpose buffer

    if (t < NPAIR * DIM) {
        int k  = t >> 3;
        int c  = t & 7;
        int g1 = i + k - (PATCH - 2);
        int g0 = i + k - (PATCH - 1);
        float v1 = (g1 >= 0) ? x[g1 * DIM + c] : 0.0f;
        float v0 = (g0 >= 0) ? x[g0 * DIM + c] : 0.0f;
        sd[k][c] = v1 - v0;
    }
    __syncthreads();

    float s1 = 0.0f, s2A = 0.0f, s2C = 0.0f;
    unsigned long long vA[8], vC[8];
    #pragma unroll
    for (int j = 0; j < 8; j++) { vA[j] = 0ull; vC[j] = 0ull; }

    const int pl = p & 7;
    if (p < 8) mainloop<true >(sd, pl, q, s1, s2A, s2C, vA, vC);
    else       mainloop<false>(sd, pl, q, s1, s2A, s2C, vA, vC);

    // ---- level-1 / level-2 outputs ----
    float* out1 = out;
    float* out2 = out + (size_t)seq_len * W;
    float* out3 = out + (size_t)seq_len * (W + W * W);

    if (q == 0) out1[(size_t)i * W + p] = s1;
    out2[(size_t)i * (W * W) + p * W + q]     = s2A;
    out2[(size_t)i * (W * W) + p * W + q + 8] = s2C;

    ulonglong2* o3 = reinterpret_cast<ulonglong2*>(out3 + (size_t)i * (W * W * W));
    const int cbase = p * 32 + q * 4;   // local chunk base of this thread's row

    // ---- phase A: cells (p, q) — output rows 16p+q ----
    #pragma unroll
    for (int s = 0; s < 4; s++)
        sbuf[swz(cbase + s)] = make_ulonglong2(vA[2 * s], vA[2 * s + 1]);
    __syncthreads();
    #pragma unroll
    for (int j = 0; j < 4; j++) {
        int c = j * 128 + t;                      // local chunk 0..511
        int g = ((c >> 5) << 6) + (c & 31);       // global chunk (b<8 rows)
        o3[g] = sbuf[swz(c)];
    }
    __syncthreads();

    // ---- phase B: cells (p, q+8) — output rows 16p+q+8 ----
    #pragma unroll
    for (int s = 0; s < 4; s++)
        sbuf[swz(cbase + s)] = make_ulonglong2(vC[2 * s], vC[2 * s + 1]);
    __syncthreads();
    #pragma unroll
    for (int j = 0; j < 4; j++) {
        int c = j * 128 + t;
        int g = ((c >> 5) << 6) + 32 + (c & 31);  // global chunk (b>=8 rows)
        o3[g] = sbuf[swz(c)];
    }
}

extern "C" void kernel_launch(void* const* d_in, const int* in_sizes, int n_in,
                              void* d_out, int out_size)
{
    const float* x   = (const float*)d_in[0];
    float*       out = (float*)d_out;
    const int seq_len = in_sizes[0] / DIM;   // 8192
    leadlag_sig_kernel<<<seq_len, 128>>>(x, out, seq_len);
}

// round 9
// speedup vs baseline: 9.2438x; 9.2438x over previous
#include <cuda_runtime.h>

static constexpr int DIM   = 8;
static constexpr int PATCH = 16;
static constexpr int NPAIR = PATCH - 1;
static constexpr int W     = 2 * DIM;
static constexpr int GRID  = 1184;        // 148 SMs x 8 resident blocks

__device__ __forceinline__ unsigned long long pack2(float lo, float hi) {
    unsigned long long r;
    asm("mov.b64 %0, {%1, %2};" : "=l"(r) : "f"(lo), "f"(hi));
    return r;
}
__device__ __forceinline__ unsigned long long fma2(unsigned long long a,
                                                   unsigned long long b,
                                                   unsigned long long c) {
    unsigned long long d;
    asm("fma.rn.f32x2 %0, %1, %2, %3;" : "=l"(d) : "l"(a), "l"(b), "l"(c));
    return d;
}

// Thread t: p = t>>3 (0..15, warp-uniform half), q = t&7. Thread owns cells
// (p,q) and (p,q+8); both share s1 = S1[p], dp = d[p&7], dq = d[q].
template <bool AL>
__device__ __forceinline__ void mainloop(
    const float (*__restrict__ sd)[DIM],
    int pl, int q,
    float& s1, float& s2A, float& s2C,
    unsigned long long* __restrict__ vA,
    unsigned long long* __restrict__ vC)
{
    #pragma unroll
    for (int k = 0; k < NPAIR; k++) {
        const ulonglong2* sdv = reinterpret_cast<const ulonglong2*>(sd[k]);
        const ulonglong2 dA = sdv[0];
        const ulonglong2 dB = sdv[1];
        const float dp = sd[k][pl];
        const float dq = sd[k][q];

        float coefAL, coefAG, coefCL, coefCG;
        if (AL) {
            // p<8: p active in LEAD. Cell A (b=q) active in LEAD, C (b=q+8) in LAG.
            float tt = dp * dq;
            float pa = s1 * dq;
            coefAL = fmaf(0.5f, pa, s2A);
            coefAL = fmaf(1.0f / 6.0f, tt, coefAL);
            coefCL = s2C;
            s2A    = s2A + pa;
            s2A    = fmaf(0.5f, tt, s2A);
            s1    += dp;
            float pc = s1 * dq;           // lag: uses updated s1
            coefAG = s2A;
            coefCG = fmaf(0.5f, pc, s2C);
            s2C   += pc;
        } else {
            // p>=8: p active in LAG.
            float pa = s1 * dq;           // lead: pre-update s1
            coefAL = fmaf(0.5f, pa, s2A);
            coefCL = s2C;
            s2A   += pa;
            coefAG = s2A;
            float tt = dp * dq;
            float pc = s1 * dq;
            coefCG = fmaf(0.5f, pc, s2C);
            coefCG = fmaf(1.0f / 6.0f, tt, coefCG);
            s2C   += pc;
            s2C    = fmaf(0.5f, tt, s2C);
            s1    += dp;
        }

        const unsigned long long cAL = pack2(coefAL, coefAL);
        const unsigned long long cAG = pack2(coefAG, coefAG);
        const unsigned long long cCL = pack2(coefCL, coefCL);
        const unsigned long long cCG = pack2(coefCG, coefCG);

        vA[0] = fma2(cAL, dA.x, vA[0]);  vA[1] = fma2(cAL, dA.y, vA[1]);
        vA[2] = fma2(cAL, dB.x, vA[2]);  vA[3] = fma2(cAL, dB.y, vA[3]);
        vA[4] = fma2(cAG, dA.x, vA[4]);  vA[5] = fma2(cAG, dA.y, vA[5]);
        vA[6] = fma2(cAG, dB.x, vA[6]);  vA[7] = fma2(cAG, dB.y, vA[7]);

        vC[0] = fma2(cCL, dA.x, vC[0]);  vC[1] = fma2(cCL, dA.y, vC[1]);
        vC[2] = fma2(cCL, dB.x, vC[2]);  vC[3] = fma2(cCL, dB.y, vC[3]);
        vC[4] = fma2(cCG, dA.x, vC[4]);  vC[5] = fma2(cCG, dA.y, vC[5]);
        vC[6] = fma2(cCG, dB.x, vC[6]);  vC[7] = fma2(cCG, dB.y, vC[7]);
    }
}

// Conflict-free chunk swizzle (verified for the fixed-p STS phases and the
// lane-linear LDS sweep). Region-preserving within 8-chunk groups, so the
// per-warp 256-chunk quarters stay warp-local.
__device__ __forceinline__ int swz(int c) {
    return c ^ ((c >> 3) & 7);
}

__global__ __launch_bounds__(128, 8)
void leadlag_sig_kernel(const float* __restrict__ x,
                        float* __restrict__ out,
                        int seq_len)
{
    const int t  = threadIdx.x;      // 0..127
    const int w  = t >> 5;           // warp 0..3
    const int l  = t & 31;           // lane
    const int p  = t >> 3;           // first index 0..15 (warp-uniform half)
    const int q  = t & 7;            // second index low part
    const int pl = p & 7;

    __shared__ __align__(16) float sd[4][NPAIR][DIM];    // per-warp deltas
    __shared__ __align__(16) ulonglong2 sbuf[1024];      // 16 KB transpose buf

    float* __restrict__ out1 = out;
    float* __restrict__ out2 = out + (size_t)seq_len * W;
    float* __restrict__ out3 = out + (size_t)seq_len * (W + W * W);

    for (int i = blockIdx.x; i < seq_len; i += GRID) {
        // ---- per-warp delta load (no block barrier) ----
        // lane m<30 produces delta float4 #m: k = m>>1, cols 4*(m&1)..
        if (l < 30) {
            int k  = l >> 1;
            int h  = (l & 1) << 2;
            int g1 = i + k - (PATCH - 2);
            int g0 = i + k - (PATCH - 1);
            float4 v1 = (g1 >= 0) ? *reinterpret_cast<const float4*>(x + g1 * DIM + h)
                                  : make_float4(0.f, 0.f, 0.f, 0.f);
            float4 v0 = (g0 >= 0) ? *reinterpret_cast<const float4*>(x + g0 * DIM + h)
                                  : make_float4(0.f, 0.f, 0.f, 0.f);
            *reinterpret_cast<float4*>(&sd[w][k][h]) =
                make_float4(v1.x - v0.x, v1.y - v0.y, v1.z - v0.z, v1.w - v0.w);
        }
        __syncwarp();

        float s1 = 0.0f, s2A = 0.0f, s2C = 0.0f;
        unsigned long long vA[8], vC[8];
        #pragma unroll
        for (int j = 0; j < 8; j++) { vA[j] = 0ull; vC[j] = 0ull; }

        if (p < 8) mainloop<true >(sd[w], pl, q, s1, s2A, s2C, vA, vC);
        else       mainloop<false>(sd[w], pl, q, s1, s2A, s2C, vA, vC);

        // ---- level-1 / level-2 outputs ----
        if (q == 0) out1[(size_t)i * W + p] = s1;
        out2[(size_t)i * (W * W) + p * W + q]     = s2A;
        out2[(size_t)i * (W * W) + p * W + q + 8] = s2C;

        // ---- warp-local transpose: stage rows into swizzled smem ----
        {
            const int rA = p * W + q;    // row of cell (p, q)
            const int rC = rA + 8;       // row of cell (p, q+8)
            #pragma unroll
            for (int s = 0; s < 4; s++) {
                sbuf[swz(4 * rA + s)] = make_ulonglong2(vA[2 * s], vA[2 * s + 1]);
                sbuf[swz(4 * rC + s)] = make_ulonglong2(vC[2 * s], vC[2 * s + 1]);
            }
        }
        __syncwarp();

        // ---- coalesced sweep of this warp's 4 KB quarter ----
        ulonglong2* o3 = reinterpret_cast<ulonglong2*>(
            out3 + (size_t)i * (W * W * W));
        #pragma unroll
        for (int j = 0; j < 8; j++) {
            int c = (w << 8) + (j << 5) + l;    // 256w + 32j + lane
            o3[c] = sbuf[swz(c)];
        }
        __syncwarp();   // protect sbuf/sd before next iteration overwrites
    }
}

extern "C" void kernel_launch(void* const* d_in, const int* in_sizes, int n_in,
                              void* d_out, int out_size)
{
    const float* x   = (const float*)d_in[0];
    float*       out = (float*)d_out;
    const int seq_len = in_sizes[0] / DIM;   // 8192
    leadlag_sig_kernel<<<GRID, 128>>>(x, out, seq_len);
}

// round 10
// speedup vs baseline: 11.6916x; 1.2648x over previous
#include <cuda_runtime.h>
#include <cuda.h>
#include <cstdint>

static constexpr int DIM   = 8;
static constexpr int PATCH = 16;
static constexpr int NPAIR = PATCH - 1;
static constexpr int W     = 2 * DIM;

__device__ __forceinline__ unsigned long long pack2(float lo, float hi) {
    unsigned long long r;
    asm("mov.b64 %0, {%1, %2};" : "=l"(r) : "f"(lo), "f"(hi));
    return r;
}
__device__ __forceinline__ unsigned long long fma2(unsigned long long a,
                                                   unsigned long long b,
                                                   unsigned long long c) {
    unsigned long long d;
    asm("fma.rn.f32x2 %0, %1, %2, %3;" : "=l"(d) : "l"(a), "l"(b), "l"(c));
    return d;
}
__device__ __forceinline__ uint32_t smem_u32(const void* p) {
    uint32_t a;
    asm("{ .reg .u64 t; cvta.to.shared.u64 t, %1; cvt.u32.u64 %0, t; }"
        : "=r"(a) : "l"(p));
    return a;
}

// Thread t: p = t>>3 (0..15, warp-uniform half), q = t&7. Thread owns cells
// (p,q) and (p,q+8); both share s1 = S1[p], dp = d[p&7], dq = d[q].
template <bool AL>
__device__ __forceinline__ void mainloop(
    const float (*__restrict__ sd)[DIM],
    int pl, int q,
    float& s1, float& s2A, float& s2C,
    unsigned long long* __restrict__ vA,
    unsigned long long* __restrict__ vC)
{
    #pragma unroll
    for (int k = 0; k < NPAIR; k++) {
        const ulonglong2* sdv = reinterpret_cast<const ulonglong2*>(sd[k]);
        const ulonglong2 dA = sdv[0];
        const ulonglong2 dB = sdv[1];
        const float dp = sd[k][pl];
        const float dq = sd[k][q];

        float coefAL, coefAG, coefCL, coefCG;
        if (AL) {
            // p<8: p active in LEAD. Cell A (b=q) active in LEAD, C (b=q+8) in LAG.
            float tt = dp * dq;
            float pa = s1 * dq;
            coefAL = fmaf(0.5f, pa, s2A);
            coefAL = fmaf(1.0f / 6.0f, tt, coefAL);
            coefCL = s2C;
            s2A    = s2A + pa;
            s2A    = fmaf(0.5f, tt, s2A);
            s1    += dp;
            float pc = s1 * dq;           // lag: uses updated s1
            coefAG = s2A;
            coefCG = fmaf(0.5f, pc, s2C);
            s2C   += pc;
        } else {
            // p>=8: p active in LAG.
            float pa = s1 * dq;           // lead: pre-update s1
            coefAL = fmaf(0.5f, pa, s2A);
            coefCL = s2C;
            s2A   += pa;
            coefAG = s2A;
            float tt = dp * dq;
            float pc = s1 * dq;
            coefCG = fmaf(0.5f, pc, s2C);
            coefCG = fmaf(1.0f / 6.0f, tt, coefCG);
            s2C   += pc;
            s2C    = fmaf(0.5f, tt, s2C);
            s1    += dp;
        }

        const unsigned long long cAL = pack2(coefAL, coefAL);
        const unsigned long long cAG = pack2(coefAG, coefAG);
        const unsigned long long cCL = pack2(coefCL, coefCL);
        const unsigned long long cCG = pack2(coefCG, coefCG);

        vA[0] = fma2(cAL, dA.x, vA[0]);  vA[1] = fma2(cAL, dA.y, vA[1]);
        vA[2] = fma2(cAL, dB.x, vA[2]);  vA[3] = fma2(cAL, dB.y, vA[3]);
        vA[4] = fma2(cAG, dA.x, vA[4]);  vA[5] = fma2(cAG, dA.y, vA[5]);
        vA[6] = fma2(cAG, dB.x, vA[6]);  vA[7] = fma2(cAG, dB.y, vA[7]);

        vC[0] = fma2(cCL, dA.x, vC[0]);  vC[1] = fma2(cCL, dA.y, vC[1]);
        vC[2] = fma2(cCL, dB.x, vC[2]);  vC[3] = fma2(cCL, dB.y, vC[3]);
        vC[4] = fma2(cCG, dA.x, vC[4]);  vC[5] = fma2(cCG, dA.y, vC[5]);
        vC[6] = fma2(cCG, dB.x, vC[6]);  vC[7] = fma2(cCG, dB.y, vC[7]);
    }
}

// 16B-chunk swizzle == TMA SW128 layout for a 128B-wide tile:
// byte ^ ((byte>>3)&0x70)  <=>  chunk ^ ((chunk>>3)&7).
// Conflict-free for the fixed-p STS phases (verified rounds 3-4).
__device__ __forceinline__ int swz(int c) {
    return c ^ ((c >> 3) & 7);
}

__global__ __launch_bounds__(128, 8)
void leadlag_sig_kernel(const float* __restrict__ x,
                        float* __restrict__ out,
                        int seq_len,
                        const __grid_constant__ CUtensorMap dmap)
{
    const int i = blockIdx.x;
    const int t = threadIdx.x;       // 0..127
    const int p = t >> 3;            // first index 0..15 (warp-uniform half)
    const int q = t & 7;             // second index low part

    __shared__ __align__(16)   float sd[NPAIR][DIM];
    __shared__ __align__(1024) ulonglong2 sbuf[1024];   // 16 KB SW128 tile

    if (t < NPAIR * DIM) {
        int k  = t >> 3;
        int c  = t & 7;
        int g1 = i + k - (PATCH - 2);
        int g0 = i + k - (PATCH - 1);
        float v1 = (g1 >= 0) ? x[g1 * DIM + c] : 0.0f;
        float v0 = (g0 >= 0) ? x[g0 * DIM + c] : 0.0f;
        sd[k][c] = v1 - v0;
    }
    __syncthreads();

    float s1 = 0.0f, s2A = 0.0f, s2C = 0.0f;
    unsigned long long vA[8], vC[8];
    #pragma unroll
    for (int j = 0; j < 8; j++) { vA[j] = 0ull; vC[j] = 0ull; }

    const int pl = p & 7;
    if (p < 8) mainloop<true >(sd, pl, q, s1, s2A, s2C, vA, vC);
    else       mainloop<false>(sd, pl, q, s1, s2A, s2C, vA, vC);

    // ---- stage level-3 rows into SW128-swizzled smem ----
    {
        const int rA = p * W + q;        // row of cell (p, q)
        const int rC = rA + 8;           // row of cell (p, q+8)
        #pragma unroll
        for (int s = 0; s < 4; s++) {
            sbuf[swz(4 * rA + s)] = make_ulonglong2(vA[2 * s], vA[2 * s + 1]);
            sbuf[swz(4 * rC + s)] = make_ulonglong2(vC[2 * s], vC[2 * s + 1]);
        }
    }

    // ---- level-1 / level-2 outputs ----
    float* out1 = out;
    float* out2 = out + (size_t)seq_len * W;

    if (q == 0) out1[(size_t)i * W + p] = s1;
    out2[(size_t)i * (W * W) + p * W + q]     = s2A;
    out2[(size_t)i * (W * W) + p * W + q + 8] = s2C;

    __syncthreads();

    // ---- level-3: single TMA tensor store (SW128 smem -> linear gmem) ----
    if (t == 0) {
        asm volatile("fence.proxy.async.shared::cta;" ::: "memory");
        uint32_t sa = smem_u32(sbuf);
        asm volatile(
            "cp.async.bulk.tensor.3d.global.shared::cta.tile.bulk_group "
            "[%0, {%1, %2, %3}], [%4];"
            :: "l"(&dmap), "r"(0), "r"(0), "r"(i), "r"(sa)
            : "memory");
        asm volatile("cp.async.bulk.commit_group;" ::: "memory");
        asm volatile("cp.async.bulk.wait_group 0;" ::: "memory");
    }
}

extern "C" void kernel_launch(void* const* d_in, const int* in_sizes, int n_in,
                              void* d_out, int out_size)
{
    const float* x   = (const float*)d_in[0];
    float*       out = (float*)d_out;
    const int seq_len = in_sizes[0] / DIM;   // 8192

    // L3 region: seq_len tiles of 128 rows x 32 f32 (128B), contiguous.
    float* out3 = out + (size_t)seq_len * (W + W * W);

    typedef CUresult (*EncodeFn)(
        CUtensorMap*, CUtensorMapDataType, cuuint32_t, void*,
        const cuuint64_t*, const cuuint64_t*, const cuuint32_t*,
        const cuuint32_t*, CUtensorMapInterleave, CUtensorMapSwizzle,
        CUtensorMapL2promotion, CUtensorMapFloatOOBfill);
    static EncodeFn encode = nullptr;
    if (!encode) {
        cudaDriverEntryPointQueryResult st;
        void* fn = nullptr;
        cudaGetDriverEntryPoint("cuTensorMapEncodeTiled", &fn,
                                cudaEnableDefault, &st);
        encode = (EncodeFn)fn;
    }

    CUtensorMap dmap;
    cuuint64_t dims[3]    = {32, 128, (cuuint64_t)seq_len};
    cuuint64_t strides[2] = {128, 16384};          // bytes
    cuuint32_t box[3]     = {32, 128, 1};
    cuuint32_t estr[3]    = {1, 1, 1};
    encode(&dmap, CU_TENSOR_MAP_DATA_TYPE_FLOAT32, 3, (void*)out3,
           dims, strides, box, estr,
           CU_TENSOR_MAP_INTERLEAVE_NONE, CU_TENSOR_MAP_SWIZZLE_128B,
           CU_TENSOR_MAP_L2_PROMOTION_L2_128B,
           CU_TENSOR_MAP_FLOAT_OOB_FILL_NONE);

    leadlag_sig_kernel<<<seq_len, 128>>>(x, out, seq_len, dmap);
}